// round 11
// baseline (speedup 1.0000x reference)
#include <cuda_runtime.h>

// DILATE loss, warp-synchronous soft-DTW wavefront.
// 256 problems (128x128, gamma=0.01). One WARP per problem: lane k owns rows
// 4k+1..4k+4; the anti-diagonal recurrence is carried entirely in registers
// with shfl for the lane-boundary cells -> no __syncthreads in the hot loops.
// R is spilled to SMEM (row stride 130) during the forward pass and re-read
// (1 LDS/cell) in the backward E-recursion; all neighbor R/E values come from
// shifted registers. CTA = 2 warps = 2 problems so the two warps land on
// different SMSPs (private MUFU pipes); 134KB smem -> 1 CTA/SM, 128 CTAs.

#define NN    128
#define RS    130
#define BV    64
#define MM    256
#define GAMMA 0.01f
#define INVG  100.0f
#define BIGV  1.0e8f

#define WARP_FLOATS (16640 + 128)   // R (127*130+128 rounded) + os

__device__ float g_partial[MM];

static __device__ __forceinline__ int clamp01(int x, int hi) {
    return x < 0 ? 0 : (x > hi ? hi : x);
}

__global__ __launch_bounds__(64, 1)
void dilate_warp_kernel(const float* __restrict__ outputs,
                        const float* __restrict__ targets) {
    extern __shared__ float sm[];
    const int wid  = threadIdx.x >> 5;
    const int lane = threadIdx.x & 31;
    const int m = blockIdx.x * 2 + wid;
    const int b = m >> 2;
    const int c = m & 3;

    float* R  = sm + wid * WARP_FLOATS;
    float* os = R + 16640;

    // ---- load series: o -> smem (random per-diag access), t -> registers
    #pragma unroll
    for (int r = 0; r < 4; ++r)
        os[4 * lane + r] = outputs[(b * NN + 4 * lane + r) * 4 + c];

    float tr[4], tp[4];
    #pragma unroll
    for (int r = 0; r < 4; ++r)
        tr[r] = targets[(b * NN + 4 * lane + r) * 4 + c];
    tp[0] = tr[1]; tp[1] = tr[2]; tp[2] = tr[3];
    tp[3] = __shfl_down_sync(0xffffffffu, tr[0], 1);   // t[i+1]; lane31 unused (i=128)
    __syncwarp();

    // =================== FORWARD ===================
    // r1 = R on diag d-1 (my rows), r2 = diag d-2, o_ = o[j-1] for diag d.
    float r1[4], r2[4], o_[4];
    #pragma unroll
    for (int r = 0; r < 4; ++r) { r1[r] = BIGV; r2[r] = BIGV; o_[r] = 0.0f; }
    if (lane == 0) o_[0] = os[0];

    for (int d = 2; d <= 2 * NN; ++d) {
        float up1 = __shfl_up_sync(0xffffffffu, r1[3], 1);  // R(d-1, i-1) for r=0
        float up2 = __shfl_up_sync(0xffffffffu, r2[3], 1);  // R(d-2, i-1) for r=0
        float o3  = __shfl_up_sync(0xffffffffu, o_[3], 1);
        if (lane == 0) { up1 = BIGV; up2 = (d == 2) ? 0.0f : BIGV; }

        float nr[4];
        #pragma unroll
        for (int r = 0; r < 4; ++r) {
            const int i = 4 * lane + r + 1;
            const int j = d - i;
            float a  = (r ? r1[r - 1] : up1);   // R[i-1][j]
            float bb = r1[r];                   // R[i][j-1]
            float cd = (r ? r2[r - 1] : up2);   // R[i-1][j-1]
            float dv = tr[r] - o_[r]; dv *= dv;
            float mn = fminf(cd, fminf(a, bb));
            float s  = __expf((mn - a)  * INVG)
                     + __expf((mn - bb) * INVG)
                     + __expf((mn - cd) * INVG);
            float val = dv + mn - GAMMA * __logf(s);
            bool valid = (j >= 1) && (j <= NN);
            if (valid) R[(i - 1) * RS + (j - 1)] = val;
            nr[r] = valid ? val : BIGV;
        }
        #pragma unroll
        for (int r = 0; r < 4; ++r) { r2[r] = r1[r]; r1[r] = nr[r]; }
        o_[3] = o_[2]; o_[2] = o_[1]; o_[1] = o_[0];
        o_[0] = (lane == 0) ? os[clamp01(d - 1, NN - 1)] : o3;
    }
    __syncwarp();   // R fully written before cross-lane backward reads

    // =================== BACKWARD ===================
    // rd1/e1 = R/E on diag d+1 (my rows), rd2/e2 = diag d+2.
    // o0 = os[j-1], o1 = os[j] for current diag d.
    float rd1[4], rd2[4], e1[4], e2[4], o0[4], o1[4];
    #pragma unroll
    for (int r = 0; r < 4; ++r) { rd1[r] = BIGV; rd2[r] = BIGV; e1[r] = 0.0f; e2[r] = 0.0f; }
    if (lane == 31) { rd1[3] = r1[3]; e1[3] = 1.0f; }   // seed E[N][N]=1, R(256,128)
    #pragma unroll
    for (int r = 0; r < 4; ++r) {
        o0[r] = os[clamp01(253 - 4 * lane - r, NN - 1)];
        o1[r] = os[clamp01(254 - 4 * lane - r, NN - 1)];
    }

    float tsum = 0.0f;
    for (int d = 2 * NN - 1; d >= 2; --d) {
        float rd1n = __shfl_down_sync(0xffffffffu, rd1[0], 1);  // R(d+1, i+1) for r=3
        float e1n  = __shfl_down_sync(0xffffffffu, e1[0], 1);
        float rd2n = __shfl_down_sync(0xffffffffu, rd2[0], 1);  // R(d+2, i+1) for r=3
        float e2n  = __shfl_down_sync(0xffffffffu, e2[0], 1);
        float o0n  = __shfl_down_sync(0xffffffffu, o0[0], 1);

        float rc[4], ec[4];
        #pragma unroll
        for (int r = 0; r < 4; ++r) {
            const int i = 4 * lane + r + 1;
            const int j = d - i;
            const bool valid = (j >= 1) && (j <= NN);
            float rij = BIGV;
            float E = 0.0f;
            if (valid) {
                rij = R[(i - 1) * RS + (j - 1)];
                float r_ij  = (r < 3) ? rd1[r + 1] : rd1n;   // R[i+1][j]
                float e_ij  = (r < 3) ? e1[r + 1]  : e1n;    // E[i+1][j]
                float r_ijj = (r < 3) ? rd2[r + 1] : rd2n;   // R[i+1][j+1]
                float e_ijj = (r < 3) ? e2[r + 1]  : e2n;    // E[i+1][j+1]
                if (i < NN) {
                    float dn = tp[r] - o0[r]; dn *= dn;
                    E += __expf((r_ij - rij - dn) * INVG) * e_ij;
                }
                if (j < NN) {
                    float dn = tr[r] - o1[r]; dn *= dn;
                    E += __expf((rd1[r] - rij - dn) * INVG) * e1[r];
                    if (i < NN) {
                        float dn2 = tp[r] - o1[r]; dn2 *= dn2;
                        E += __expf((r_ijj - rij - dn2) * INVG) * e_ijj;
                    }
                }
                float dd = (float)(i - j);
                tsum += E * dd * dd;
            }
            rc[r] = rij;
            ec[r] = E;
        }
        #pragma unroll
        for (int r = 0; r < 4; ++r) { rd2[r] = rd1[r]; rd1[r] = rc[r]; e2[r] = e1[r]; e1[r] = ec[r]; }
        // o shift: o1 <- o0, o0 slides one index down (new value enters at lane31 r=3)
        float n0 = o0[1], n1 = o0[2], n2 = o0[3];
        float n3 = (lane == 31) ? os[clamp01(d - 130, NN - 1)] : o0n;
        o1[0] = o0[0]; o1[1] = o0[1]; o1[2] = o0[2]; o1[3] = o0[3];
        o0[0] = n0; o0[1] = n1; o0[2] = n2; o0[3] = n3;
    }

    // ---- warp reduce tsum, combine with R[N][N]
    #pragma unroll
    for (int o = 16; o; o >>= 1)
        tsum += __shfl_xor_sync(0xffffffffu, tsum, o);
    if (lane == 0) {
        float rnn = R[(NN - 1) * RS + (NN - 1)];
        g_partial[m] = 0.5f * rnn * (1.0f / BV)
                     + 0.5f * tsum * (1.0f / (BV * (float)NN * (float)NN));
    }
}

__global__ void dilate_reduce_kernel(float* __restrict__ out) {
    __shared__ float s[MM];
    int t = threadIdx.x;
    s[t] = g_partial[t];
    __syncthreads();
    #pragma unroll
    for (int o = MM / 2; o; o >>= 1) {
        if (t < o) s[t] += s[t + o];
        __syncthreads();
    }
    if (t == 0) out[0] = s[0];
}

extern "C" void kernel_launch(void* const* d_in, const int* in_sizes, int n_in,
                              void* d_out, int out_size) {
    const float* outputs = (const float*)d_in[0];
    const float* targets = (const float*)d_in[1];
    float* out = (float*)d_out;

    const int smem_bytes = 2 * WARP_FLOATS * (int)sizeof(float);
    cudaFuncSetAttribute(dilate_warp_kernel,
                         cudaFuncAttributeMaxDynamicSharedMemorySize, smem_bytes);

    dilate_warp_kernel<<<MM / 2, 64, smem_bytes>>>(outputs, targets);
    dilate_reduce_kernel<<<1, MM>>>(out);
}